// round 1
// baseline (speedup 1.0000x reference)
#include <cuda_runtime.h>
#include <cstdint>

#define WPB 8          // warps per block
#define EPW 4          // elements per warp
#define NTHREADS 256
#define D 64
#define NS 8

__device__ __forceinline__ unsigned long long pack2(float x, float y){
    unsigned long long r;
    asm("mov.b64 %0, {%1, %2};" : "=l"(r)
        : "r"(__float_as_uint(x)), "r"(__float_as_uint(y)));
    return r;
}
__device__ __forceinline__ void unpack2(unsigned long long p, float &x, float &y){
    unsigned int lo, hi;
    asm("mov.b64 {%0, %1}, %2;" : "=r"(lo), "=r"(hi) : "l"(p));
    x = __uint_as_float(lo); y = __uint_as_float(hi);
}
// packed fp32x2 FMA (Blackwell): acc = a*b + acc
__device__ __forceinline__ void ffma2(unsigned long long &acc,
                                      unsigned long long a, unsigned long long b){
    asm("fma.rn.f32x2 %0, %1, %2, %3;" : "=l"(acc) : "l"(a), "l"(b), "l"(acc));
}

__device__ __forceinline__ void softmax8(float* w){
    float m = w[0];
    #pragma unroll
    for (int s = 1; s < NS; s++) m = fmaxf(m, w[s]);
    float sum = 0.f;
    #pragma unroll
    for (int s = 0; s < NS; s++){ w[s] = __expf(w[s] - m); sum += w[s]; }
    float inv = 1.f / sum;
    #pragma unroll
    for (int s = 0; s < NS; s++) w[s] *= inv;
}

__global__ void __launch_bounds__(NTHREADS)
sestkgcn_kernel(
    const int* __restrict__ u, const int* __restrict__ v,
    const float* __restrict__ usr_feat, const float* __restrict__ item_feat,
    const float* __restrict__ rel_feat,
    const int* __restrict__ neigh_uu, const float* __restrict__ uu_st,
    const int* __restrict__ neigh_ui, const float* __restrict__ ui_rat,
    const float* __restrict__ ui_vot, const float* __restrict__ ui_tim,
    const int* __restrict__ neigh_iu, const float* __restrict__ iu_rat,
    const float* __restrict__ iu_vot, const float* __restrict__ iu_tim,
    const int* __restrict__ neigh_ii, const int* __restrict__ neigh_ir,
    const float* __restrict__ Wu, const float* __restrict__ bu,
    const float* __restrict__ Wv, const float* __restrict__ bv,
    float* __restrict__ out, int batch)
{
    __shared__ float sWu[D*D];              // row-major [d][j]
    __shared__ float sWv[D*D];
    __shared__ float sb[2*D];               // bu | bv
    __shared__ float sx[WPB][EPW][D];       // staged x vectors

    for (int i = threadIdx.x; i < D*D; i += NTHREADS){
        sWu[i] = Wu[i];
        sWv[i] = Wv[i];
    }
    if (threadIdx.x < D)        sb[threadIdx.x] = bu[threadIdx.x];
    else if (threadIdx.x < 2*D) sb[threadIdx.x] = bv[threadIdx.x - D];
    __syncthreads();

    const int warp = threadIdx.x >> 5;
    const int lane = threadIdx.x & 31;
    const int base = (blockIdx.x * WPB + warp) * EPW;

    const float2* usr2  = (const float2*)usr_feat;   // vector base = id*32 + lane
    const float2* item2 = (const float2*)item_feat;
    const float2* rel2  = (const float2*)rel_feat;

    unsigned long long uepk[EPW];     // u_emb pair (d=2l, 2l+1), needed for KG attention
    float uh0[EPW], uh1[EPW];         // user_h
    float vh0[EPW], vh1[EPW];         // item_h

    // =============== user side: gather + aggregate ===============
    #pragma unroll
    for (int e = 0; e < EPW; e++){
        int b = base + e; if (b >= batch) b = batch - 1;
        const int uid = u[b];
        float2 ue = usr2[uid*32 + lane];
        uepk[e] = pack2(ue.x, ue.y);
        float ax = ue.x, ay = ue.y;

        // ---- social neighbors (softmax over tie strength) ----
        {
            const float4* stp = (const float4*)(uu_st + uid*NS);
            float4 s0 = stp[0], s1 = stp[1];
            float w[NS] = {s0.x,s0.y,s0.z,s0.w, s1.x,s1.y,s1.z,s1.w};
            softmax8(w);
            const int4* ip = (const int4*)(neigh_uu + uid*NS);
            int4 i0 = ip[0], i1 = ip[1];
            int idx[NS] = {i0.x,i0.y,i0.z,i0.w, i1.x,i1.y,i1.z,i1.w};
            #pragma unroll
            for (int s = 0; s < NS; s++){
                float2 f = usr2[idx[s]*32 + lane];
                ax = fmaf(w[s], f.x, ax);
                ay = fmaf(w[s], f.y, ay);
            }
        }
        // ---- interacted items (softmax over rat*vot*tim) ----
        {
            const float4* rp = (const float4*)(ui_rat + uid*NS);
            const float4* vp = (const float4*)(ui_vot + uid*NS);
            const float4* tp = (const float4*)(ui_tim + uid*NS);
            float4 r0 = rp[0], r1 = rp[1];
            float4 q0 = vp[0], q1 = vp[1];
            float4 t0 = tp[0], t1 = tp[1];
            float w[NS] = { r0.x*q0.x*t0.x, r0.y*q0.y*t0.y, r0.z*q0.z*t0.z, r0.w*q0.w*t0.w,
                            r1.x*q1.x*t1.x, r1.y*q1.y*t1.y, r1.z*q1.z*t1.z, r1.w*q1.w*t1.w };
            softmax8(w);
            const int4* ip = (const int4*)(neigh_ui + uid*NS);
            int4 i0 = ip[0], i1 = ip[1];
            int idx[NS] = {i0.x,i0.y,i0.z,i0.w, i1.x,i1.y,i1.z,i1.w};
            #pragma unroll
            for (int s = 0; s < NS; s++){
                float2 f = item2[idx[s]*32 + lane];
                ax = fmaf(w[s], f.x, ax);
                ay = fmaf(w[s], f.y, ay);
            }
        }
        ((float2*)&sx[warp][e][0])[lane] = make_float2(ax, ay);
    }
    __syncwarp();

    // =============== user matvec: relu(x @ Wu + bu), batched over EPW ===============
    {
        unsigned long long acc[EPW];
        unsigned long long b0 = pack2(sb[2*lane], sb[2*lane + 1]);
        #pragma unroll
        for (int e = 0; e < EPW; e++) acc[e] = b0;
        const unsigned long long* W64 = (const unsigned long long*)sWu;
        #pragma unroll 8
        for (int d = 0; d < D; d++){
            unsigned long long wv = W64[d*32 + lane];   // (W[d][2l], W[d][2l+1])
            #pragma unroll
            for (int e = 0; e < EPW; e++){
                float xv = sx[warp][e][d];
                ffma2(acc[e], wv, pack2(xv, xv));
            }
        }
        #pragma unroll
        for (int e = 0; e < EPW; e++){
            float a, bq; unpack2(acc[e], a, bq);
            uh0[e] = fmaxf(a, 0.f);
            uh1[e] = fmaxf(bq, 0.f);
        }
    }
    __syncwarp();   // matvec reads of sx done before item phase overwrites it

    // =============== item side: gather + aggregate ===============
    #pragma unroll
    for (int e = 0; e < EPW; e++){
        int b = base + e; if (b >= batch) b = batch - 1;
        const int vid = v[b];
        float2 ve = item2[vid*32 + lane];
        float ax = ve.x, ay = ve.y;

        // ---- interacting users (softmax over rat*vot*tim) ----
        {
            const float4* rp = (const float4*)(iu_rat + vid*NS);
            const float4* vp = (const float4*)(iu_vot + vid*NS);
            const float4* tp = (const float4*)(iu_tim + vid*NS);
            float4 r0 = rp[0], r1 = rp[1];
            float4 q0 = vp[0], q1 = vp[1];
            float4 t0 = tp[0], t1 = tp[1];
            float w[NS] = { r0.x*q0.x*t0.x, r0.y*q0.y*t0.y, r0.z*q0.z*t0.z, r0.w*q0.w*t0.w,
                            r1.x*q1.x*t1.x, r1.y*q1.y*t1.y, r1.z*q1.z*t1.z, r1.w*q1.w*t1.w };
            softmax8(w);
            const int4* ip = (const int4*)(neigh_iu + vid*NS);
            int4 i0 = ip[0], i1 = ip[1];
            int idx[NS] = {i0.x,i0.y,i0.z,i0.w, i1.x,i1.y,i1.z,i1.w};
            #pragma unroll
            for (int s = 0; s < NS; s++){
                float2 f = usr2[idx[s]*32 + lane];
                ax = fmaf(w[s], f.x, ax);
                ay = fmaf(w[s], f.y, ay);
            }
        }
        // ---- KG neighbors with user-relation attention ----
        {
            const int4* ip = (const int4*)(neigh_ii + vid*NS);
            const int4* rp = (const int4*)(neigh_ir + vid*NS);
            int4 i0 = ip[0], i1 = ip[1];
            int4 r0 = rp[0], r1 = rp[1];
            int iidx[NS] = {i0.x,i0.y,i0.z,i0.w, i1.x,i1.y,i1.z,i1.w};
            int ridx[NS] = {r0.x,r0.y,r0.z,r0.w, r1.x,r1.y,r1.z,r1.w};
            float ux, uy; unpack2(uepk[e], ux, uy);
            float att[NS];
            #pragma unroll
            for (int s = 0; s < NS; s++){
                float2 rf = rel2[ridx[s]*32 + lane];
                float p = fmaf(ux, rf.x, uy * rf.y);
                #pragma unroll
                for (int o = 16; o; o >>= 1) p += __shfl_xor_sync(0xffffffffu, p, o);
                att[s] = p;
            }
            softmax8(att);
            #pragma unroll
            for (int s = 0; s < NS; s++){
                float2 f = item2[iidx[s]*32 + lane];
                ax = fmaf(att[s], f.x, ax);
                ay = fmaf(att[s], f.y, ay);
            }
        }
        ((float2*)&sx[warp][e][0])[lane] = make_float2(ax, ay);
    }
    __syncwarp();

    // =============== item matvec: relu(x @ Wv + bv), batched over EPW ===============
    {
        unsigned long long acc[EPW];
        unsigned long long b0 = pack2(sb[D + 2*lane], sb[D + 2*lane + 1]);
        #pragma unroll
        for (int e = 0; e < EPW; e++) acc[e] = b0;
        const unsigned long long* W64 = (const unsigned long long*)sWv;
        #pragma unroll 8
        for (int d = 0; d < D; d++){
            unsigned long long wv = W64[d*32 + lane];
            #pragma unroll
            for (int e = 0; e < EPW; e++){
                float xv = sx[warp][e][d];
                ffma2(acc[e], wv, pack2(xv, xv));
            }
        }
        #pragma unroll
        for (int e = 0; e < EPW; e++){
            float a, bq; unpack2(acc[e], a, bq);
            vh0[e] = fmaxf(a, 0.f);
            vh1[e] = fmaxf(bq, 0.f);
        }
    }

    // =============== score: sigmoid(dot(user_h, item_h)) * 5 ===============
    #pragma unroll
    for (int e = 0; e < EPW; e++){
        float p = fmaf(uh0[e], vh0[e], uh1[e] * vh1[e]);
        #pragma unroll
        for (int o = 16; o; o >>= 1) p += __shfl_xor_sync(0xffffffffu, p, o);
        if (lane == 0 && base + e < batch)
            out[base + e] = 5.f / (1.f + __expf(-p));
    }
}

extern "C" void kernel_launch(void* const* d_in, const int* in_sizes, int n_in,
                              void* d_out, int out_size)
{
    (void)n_in; (void)out_size;
    const int batch = in_sizes[0];
    const int blocks = (batch + WPB*EPW - 1) / (WPB*EPW);
    sestkgcn_kernel<<<blocks, NTHREADS>>>(
        (const int*)d_in[0],  (const int*)d_in[1],
        (const float*)d_in[2], (const float*)d_in[3], (const float*)d_in[4],
        (const int*)d_in[5],  (const float*)d_in[6],
        (const int*)d_in[7],  (const float*)d_in[8],  (const float*)d_in[9],  (const float*)d_in[10],
        (const int*)d_in[11], (const float*)d_in[12], (const float*)d_in[13], (const float*)d_in[14],
        (const int*)d_in[15], (const int*)d_in[16],
        (const float*)d_in[17], (const float*)d_in[18],
        (const float*)d_in[19], (const float*)d_in[20],
        (float*)d_out, batch);
}

// round 2
// speedup vs baseline: 1.0172x; 1.0172x over previous
#include <cuda_runtime.h>
#include <cstdint>

#define WPB 8          // warps per block
#define EPW 4          // elements per warp
#define NTHREADS 256
#define D 64
#define NS 8

typedef unsigned long long ull;

__device__ __forceinline__ ull pack2(float x, float y){
    ull r;
    asm("mov.b64 %0, {%1, %2};" : "=l"(r)
        : "r"(__float_as_uint(x)), "r"(__float_as_uint(y)));
    return r;
}
__device__ __forceinline__ void unpack2(ull p, float &x, float &y){
    unsigned int lo, hi;
    asm("mov.b64 {%0, %1}, %2;" : "=r"(lo), "=r"(hi) : "l"(p));
    x = __uint_as_float(lo); y = __uint_as_float(hi);
}
// packed fp32x2 FMA (Blackwell): acc = a*b + acc
__device__ __forceinline__ void ffma2(ull &acc, ull a, ull b){
    asm("fma.rn.f32x2 %0, %1, %2, %3;" : "=l"(acc) : "l"(a), "l"(b), "l"(acc));
}

__device__ __forceinline__ void softmax8(float* w){
    float m = w[0];
    #pragma unroll
    for (int s = 1; s < NS; s++) m = fmaxf(m, w[s]);
    float sum = 0.f;
    #pragma unroll
    for (int s = 0; s < NS; s++){ w[s] = __expf(w[s] - m); sum += w[s]; }
    float inv = 1.f / sum;
    #pragma unroll
    for (int s = 0; s < NS; s++) w[s] *= inv;
}

// shuffle-broadcast matvec: out(pair per lane) = bias + x @ W, x packed per-lane
__device__ __forceinline__ void matvec(const ull* __restrict__ W64, ull bias,
                                       const ull* x, ull* h, int lane){
    ull acc[EPW];
    #pragma unroll
    for (int e = 0; e < EPW; e++) acc[e] = bias;
    #pragma unroll 4
    for (int dd = 0; dd < D/2; dd++){
        ull w0 = W64[(2*dd)  * 32 + lane];   // (W[2dd][2l],   W[2dd][2l+1])
        ull w1 = W64[(2*dd+1)* 32 + lane];
        #pragma unroll
        for (int e = 0; e < EPW; e++){
            ull xp = __shfl_sync(0xffffffffu, x[e], dd);
            float x0, x1; unpack2(xp, x0, x1);
            ffma2(acc[e], w0, pack2(x0, x0));
            ffma2(acc[e], w1, pack2(x1, x1));
        }
    }
    #pragma unroll
    for (int e = 0; e < EPW; e++){
        float a, b; unpack2(acc[e], a, b);
        h[e] = pack2(fmaxf(a, 0.f), fmaxf(b, 0.f));
    }
}

__global__ void __launch_bounds__(NTHREADS, 5)
sestkgcn_kernel(
    const int* __restrict__ u, const int* __restrict__ v,
    const float* __restrict__ usr_feat, const float* __restrict__ item_feat,
    const float* __restrict__ rel_feat,
    const int* __restrict__ neigh_uu, const float* __restrict__ uu_st,
    const int* __restrict__ neigh_ui, const float* __restrict__ ui_rat,
    const float* __restrict__ ui_vot, const float* __restrict__ ui_tim,
    const int* __restrict__ neigh_iu, const float* __restrict__ iu_rat,
    const float* __restrict__ iu_vot, const float* __restrict__ iu_tim,
    const int* __restrict__ neigh_ii, const int* __restrict__ neigh_ir,
    const float* __restrict__ Wu, const float* __restrict__ bu,
    const float* __restrict__ Wv, const float* __restrict__ bv,
    float* __restrict__ out, int batch)
{
    __shared__ float sWu[D*D];              // row-major [d][j]
    __shared__ float sWv[D*D];

    for (int i = threadIdx.x; i < D*D; i += NTHREADS){
        sWu[i] = Wu[i];
        sWv[i] = Wv[i];
    }
    __syncthreads();

    const int warp = threadIdx.x >> 5;
    const int lane = threadIdx.x & 31;
    const int base = (blockIdx.x * WPB + warp) * EPW;

    const float2* usr2  = (const float2*)usr_feat;   // vector base = id*32 + lane
    const float2* item2 = (const float2*)item_feat;
    const float2* rel2  = (const float2*)rel_feat;

    // hoist id loads + u_emb gathers: get all dependent chains in flight early
    int uid[EPW], vid[EPW];
    #pragma unroll
    for (int e = 0; e < EPW; e++){
        int b = base + e; if (b >= batch) b = batch - 1;
        uid[e] = u[b];
        vid[e] = v[b];
    }
    ull uepk[EPW];
    #pragma unroll
    for (int e = 0; e < EPW; e++){
        float2 ue = usr2[uid[e]*32 + lane];
        uepk[e] = pack2(ue.x, ue.y);
    }

    ull xpk[EPW];   // aggregated vector (pair per lane), reused user->item
    ull uh[EPW], vh[EPW];

    // =============== user side: gather + aggregate ===============
    #pragma unroll
    for (int e = 0; e < EPW; e++){
        float ax, ay; unpack2(uepk[e], ax, ay);

        // ---- social neighbors (softmax over tie strength) ----
        {
            const float4* stp = (const float4*)(uu_st + uid[e]*NS);
            const int4*   ip  = (const int4*)(neigh_uu + uid[e]*NS);
            float4 s0 = stp[0], s1 = stp[1];
            int4 i0 = ip[0], i1 = ip[1];
            float w[NS] = {s0.x,s0.y,s0.z,s0.w, s1.x,s1.y,s1.z,s1.w};
            softmax8(w);
            int idx[NS] = {i0.x,i0.y,i0.z,i0.w, i1.x,i1.y,i1.z,i1.w};
            #pragma unroll
            for (int s = 0; s < NS; s++){
                float2 f = usr2[idx[s]*32 + lane];
                ax = fmaf(w[s], f.x, ax);
                ay = fmaf(w[s], f.y, ay);
            }
        }
        // ---- interacted items (softmax over rat*vot*tim) ----
        {
            const float4* rp = (const float4*)(ui_rat + uid[e]*NS);
            const float4* vp = (const float4*)(ui_vot + uid[e]*NS);
            const float4* tp = (const float4*)(ui_tim + uid[e]*NS);
            const int4*   ip = (const int4*)(neigh_ui + uid[e]*NS);
            float4 r0 = rp[0], r1 = rp[1];
            float4 q0 = vp[0], q1 = vp[1];
            float4 t0 = tp[0], t1 = tp[1];
            int4 i0 = ip[0], i1 = ip[1];
            float w[NS] = { r0.x*q0.x*t0.x, r0.y*q0.y*t0.y, r0.z*q0.z*t0.z, r0.w*q0.w*t0.w,
                            r1.x*q1.x*t1.x, r1.y*q1.y*t1.y, r1.z*q1.z*t1.z, r1.w*q1.w*t1.w };
            softmax8(w);
            int idx[NS] = {i0.x,i0.y,i0.z,i0.w, i1.x,i1.y,i1.z,i1.w};
            #pragma unroll
            for (int s = 0; s < NS; s++){
                float2 f = item2[idx[s]*32 + lane];
                ax = fmaf(w[s], f.x, ax);
                ay = fmaf(w[s], f.y, ay);
            }
        }
        xpk[e] = pack2(ax, ay);
    }

    // =============== user matvec: relu(x @ Wu + bu) ===============
    matvec((const ull*)sWu, ((const ull*)bu)[lane], xpk, uh, lane);

    // =============== item side: gather + aggregate ===============
    #pragma unroll
    for (int e = 0; e < EPW; e++){
        float2 ve = item2[vid[e]*32 + lane];
        float ax = ve.x, ay = ve.y;

        // ---- interacting users (softmax over rat*vot*tim) ----
        {
            const float4* rp = (const float4*)(iu_rat + vid[e]*NS);
            const float4* vp = (const float4*)(iu_vot + vid[e]*NS);
            const float4* tp = (const float4*)(iu_tim + vid[e]*NS);
            const int4*   ip = (const int4*)(neigh_iu + vid[e]*NS);
            float4 r0 = rp[0], r1 = rp[1];
            float4 q0 = vp[0], q1 = vp[1];
            float4 t0 = tp[0], t1 = tp[1];
            int4 i0 = ip[0], i1 = ip[1];
            float w[NS] = { r0.x*q0.x*t0.x, r0.y*q0.y*t0.y, r0.z*q0.z*t0.z, r0.w*q0.w*t0.w,
                            r1.x*q1.x*t1.x, r1.y*q1.y*t1.y, r1.z*q1.z*t1.z, r1.w*q1.w*t1.w };
            softmax8(w);
            int idx[NS] = {i0.x,i0.y,i0.z,i0.w, i1.x,i1.y,i1.z,i1.w};
            #pragma unroll
            for (int s = 0; s < NS; s++){
                float2 f = usr2[idx[s]*32 + lane];
                ax = fmaf(w[s], f.x, ax);
                ay = fmaf(w[s], f.y, ay);
            }
        }
        // ---- KG neighbors with user-relation attention ----
        {
            const int4* ip = (const int4*)(neigh_ii + vid[e]*NS);
            const int4* rp = (const int4*)(neigh_ir + vid[e]*NS);
            int4 i0 = ip[0], i1 = ip[1];
            int4 r0 = rp[0], r1 = rp[1];
            int iidx[NS] = {i0.x,i0.y,i0.z,i0.w, i1.x,i1.y,i1.z,i1.w};
            int ridx[NS] = {r0.x,r0.y,r0.z,r0.w, r1.x,r1.y,r1.z,r1.w};
            float ux, uy; unpack2(uepk[e], ux, uy);
            float att[NS];
            #pragma unroll
            for (int s = 0; s < NS; s++){
                float2 rf = rel2[ridx[s]*32 + lane];
                float p = fmaf(ux, rf.x, uy * rf.y);
                #pragma unroll
                for (int o = 16; o; o >>= 1) p += __shfl_xor_sync(0xffffffffu, p, o);
                att[s] = p;
            }
            softmax8(att);
            #pragma unroll
            for (int s = 0; s < NS; s++){
                float2 f = item2[iidx[s]*32 + lane];
                ax = fmaf(att[s], f.x, ax);
                ay = fmaf(att[s], f.y, ay);
            }
        }
        xpk[e] = pack2(ax, ay);
    }

    // =============== item matvec: relu(x @ Wv + bv) ===============
    matvec((const ull*)sWv, ((const ull*)bv)[lane], xpk, vh, lane);

    // =============== score: sigmoid(dot(user_h, item_h)) * 5 ===============
    #pragma unroll
    for (int e = 0; e < EPW; e++){
        float a0, a1, b0, b1;
        unpack2(uh[e], a0, a1);
        unpack2(vh[e], b0, b1);
        float p = fmaf(a0, b0, a1 * b1);
        #pragma unroll
        for (int o = 16; o; o >>= 1) p += __shfl_xor_sync(0xffffffffu, p, o);
        if (lane == 0 && base + e < batch)
            out[base + e] = 5.f / (1.f + __expf(-p));
    }
}

extern "C" void kernel_launch(void* const* d_in, const int* in_sizes, int n_in,
                              void* d_out, int out_size)
{
    (void)n_in; (void)out_size;
    const int batch = in_sizes[0];
    const int blocks = (batch + WPB*EPW - 1) / (WPB*EPW);
    sestkgcn_kernel<<<blocks, NTHREADS>>>(
        (const int*)d_in[0],  (const int*)d_in[1],
        (const float*)d_in[2], (const float*)d_in[3], (const float*)d_in[4],
        (const int*)d_in[5],  (const float*)d_in[6],
        (const int*)d_in[7],  (const float*)d_in[8],  (const float*)d_in[9],  (const float*)d_in[10],
        (const int*)d_in[11], (const float*)d_in[12], (const float*)d_in[13], (const float*)d_in[14],
        (const int*)d_in[15], (const int*)d_in[16],
        (const float*)d_in[17], (const float*)d_in[18],
        (const float*)d_in[19], (const float*)d_in[20],
        (float*)d_out, batch);
}

// round 3
// speedup vs baseline: 1.3828x; 1.3594x over previous
#include <cuda_runtime.h>
#include <cstdint>

#define WPB 8          // warps per block
#define EPW 4          // elements per warp
#define NTHREADS 256
#define D 64
#define NS 8

typedef unsigned long long ull;

__device__ __forceinline__ ull pack2(float x, float y){
    ull r;
    asm("mov.b64 %0, {%1, %2};" : "=l"(r)
        : "r"(__float_as_uint(x)), "r"(__float_as_uint(y)));
    return r;
}
__device__ __forceinline__ void unpack2(ull p, float &x, float &y){
    unsigned int lo, hi;
    asm("mov.b64 {%0, %1}, %2;" : "=r"(lo), "=r"(hi) : "l"(p));
    x = __uint_as_float(lo); y = __uint_as_float(hi);
}
// packed fp32x2 ops (Blackwell)
__device__ __forceinline__ void ffma2(ull &acc, ull a, ull b){
    asm("fma.rn.f32x2 %0, %1, %2, %3;" : "=l"(acc) : "l"(a), "l"(b), "l"(acc));
}
__device__ __forceinline__ ull add2(ull a, ull b){
    ull r; asm("add.rn.f32x2 %0, %1, %2;" : "=l"(r) : "l"(a), "l"(b));
    return r;
}

// softmax over 8-lane group (lanes e*8 .. e*8+7), one value per lane
__device__ __forceinline__ float gsoftmax8(float x){
    float m = x;
    m = fmaxf(m, __shfl_xor_sync(0xffffffffu, m, 1));
    m = fmaxf(m, __shfl_xor_sync(0xffffffffu, m, 2));
    m = fmaxf(m, __shfl_xor_sync(0xffffffffu, m, 4));
    float e = __expf(x - m);
    float sm = e;
    sm += __shfl_xor_sync(0xffffffffu, sm, 1);
    sm += __shfl_xor_sync(0xffffffffu, sm, 2);
    sm += __shfl_xor_sync(0xffffffffu, sm, 4);
    return e / sm;
}

// replicated 8-way softmax (for attention scores already held by every lane)
__device__ __forceinline__ void softmax8(float* w){
    float m = w[0];
    #pragma unroll
    for (int s = 1; s < NS; s++) m = fmaxf(m, w[s]);
    float sum = 0.f;
    #pragma unroll
    for (int s = 0; s < NS; s++){ w[s] = __expf(w[s] - m); sum += w[s]; }
    float inv = 1.f / sum;
    #pragma unroll
    for (int s = 0; s < NS; s++) w[s] *= inv;
}

// matvec with W from gmem (L1-resident) and duplicated-pair x from smem.
// acc(pair per lane) = relu(bias + x @ W)
__device__ __forceinline__ void matvec(const ull* __restrict__ Wg,
                                       const ull* __restrict__ bg,
                                       const ull* sxe, ull* h, int lane){
    ull bias = bg[lane];
    ull acc[EPW];
    #pragma unroll
    for (int e = 0; e < EPW; e++) acc[e] = bias;
    #pragma unroll 8
    for (int d = 0; d < D; d++){
        ull wv = Wg[d*32 + lane];       // (W[d][2l], W[d][2l+1])
        #pragma unroll
        for (int e = 0; e < EPW; e++)
            ffma2(acc[e], wv, sxe[e*D + d]);   // (x[d],x[d]) broadcast
    }
    #pragma unroll
    for (int e = 0; e < EPW; e++){
        float a, b; unpack2(acc[e], a, b);
        h[e] = pack2(fmaxf(a, 0.f), fmaxf(b, 0.f));
    }
}

__global__ void __launch_bounds__(NTHREADS, 5)
sestkgcn_kernel(
    const int* __restrict__ u, const int* __restrict__ v,
    const float* __restrict__ usr_feat, const float* __restrict__ item_feat,
    const float* __restrict__ rel_feat,
    const int* __restrict__ neigh_uu, const float* __restrict__ uu_st,
    const int* __restrict__ neigh_ui, const float* __restrict__ ui_rat,
    const float* __restrict__ ui_vot, const float* __restrict__ ui_tim,
    const int* __restrict__ neigh_iu, const float* __restrict__ iu_rat,
    const float* __restrict__ iu_vot, const float* __restrict__ iu_tim,
    const int* __restrict__ neigh_ii, const int* __restrict__ neigh_ir,
    const float* __restrict__ Wu, const float* __restrict__ bu,
    const float* __restrict__ Wv, const float* __restrict__ bv,
    float* __restrict__ out, int batch)
{
    __shared__ ull sxd[WPB][EPW][D];    // duplicated-pair x vectors, 16KB

    const int warp = threadIdx.x >> 5;
    const int lane = threadIdx.x & 31;
    const int base = (blockIdx.x * WPB + warp) * EPW;

    const float2* usr2  = (const float2*)usr_feat;   // vector base = id*32 + lane
    const float2* item2 = (const float2*)item_feat;
    const float2* rel2  = (const float2*)rel_feat;

    // ---------- lane-parallel weights & indices: lane = (e = lane>>3, s = lane&7) ----------
    const int eg = lane >> 3, sg = lane & 7;
    int bb = base + eg; if (bb >= batch) bb = batch - 1;
    const int myu = u[bb];
    const int myv = v[bb];

    float w_uu = uu_st[myu*NS + sg];
    int   i_uu = neigh_uu[myu*NS + sg];
    float w_ui = ui_rat[myu*NS + sg] * ui_vot[myu*NS + sg] * ui_tim[myu*NS + sg];
    int   i_ui = neigh_ui[myu*NS + sg];
    float w_iu = iu_rat[myv*NS + sg] * iu_vot[myv*NS + sg] * iu_tim[myv*NS + sg];
    int   i_iu = neigh_iu[myv*NS + sg];
    int   i_ii = neigh_ii[myv*NS + sg];
    int   i_ir = neigh_ir[myv*NS + sg];

    w_uu = gsoftmax8(w_uu);
    w_ui = gsoftmax8(w_ui);
    w_iu = gsoftmax8(w_iu);

    const ull p_uu = pack2(w_uu, __int_as_float(i_uu));
    const ull p_ui = pack2(w_ui, __int_as_float(i_ui));
    const ull p_iu = pack2(w_iu, __int_as_float(i_iu));
    const ull p_ii = pack2(__int_as_float(i_ii), __int_as_float(i_ir));

    // ---------- u_emb gathers (needed for KG attention too) ----------
    ull uepk[EPW];
    #pragma unroll
    for (int e = 0; e < EPW; e++){
        int ue_id = __shfl_sync(0xffffffffu, myu, e << 3);
        float2 t = usr2[ue_id*32 + lane];
        uepk[e] = pack2(t.x, t.y);
    }

    // =============== user side: gather + aggregate ===============
    #pragma unroll
    for (int e = 0; e < EPW; e++){
        float ax, ay; unpack2(uepk[e], ax, ay);

        // social neighbors
        {
            float w[NS]; float2 f[NS];
            #pragma unroll
            for (int s = 0; s < NS; s++){
                ull t = __shfl_sync(0xffffffffu, p_uu, (e << 3) + s);
                float wf, idf; unpack2(t, wf, idf);
                w[s] = wf;
                f[s] = usr2[__float_as_int(idf)*32 + lane];
            }
            #pragma unroll
            for (int s = 0; s < NS; s++){
                ax = fmaf(w[s], f[s].x, ax);
                ay = fmaf(w[s], f[s].y, ay);
            }
        }
        // interacted items
        {
            float w[NS]; float2 f[NS];
            #pragma unroll
            for (int s = 0; s < NS; s++){
                ull t = __shfl_sync(0xffffffffu, p_ui, (e << 3) + s);
                float wf, idf; unpack2(t, wf, idf);
                w[s] = wf;
                f[s] = item2[__float_as_int(idf)*32 + lane];
            }
            #pragma unroll
            for (int s = 0; s < NS; s++){
                ax = fmaf(w[s], f[s].x, ax);
                ay = fmaf(w[s], f[s].y, ay);
            }
        }
        sxd[warp][e][2*lane]     = pack2(ax, ax);
        sxd[warp][e][2*lane + 1] = pack2(ay, ay);
    }
    __syncwarp();

    // =============== user matvec ===============
    ull uh[EPW];
    matvec((const ull*)Wu, (const ull*)bu, &sxd[warp][0][0], uh, lane);
    __syncwarp();   // matvec reads done before item phase overwrites sxd

    // =============== item side: gather + aggregate ===============
    #pragma unroll
    for (int e = 0; e < EPW; e++){
        int ve_id = __shfl_sync(0xffffffffu, myv, e << 3);
        float2 vt = item2[ve_id*32 + lane];
        float ax = vt.x, ay = vt.y;

        // interacting users
        {
            float w[NS]; float2 f[NS];
            #pragma unroll
            for (int s = 0; s < NS; s++){
                ull t = __shfl_sync(0xffffffffu, p_iu, (e << 3) + s);
                float wf, idf; unpack2(t, wf, idf);
                w[s] = wf;
                f[s] = usr2[__float_as_int(idf)*32 + lane];
            }
            #pragma unroll
            for (int s = 0; s < NS; s++){
                ax = fmaf(w[s], f[s].x, ax);
                ay = fmaf(w[s], f[s].y, ay);
            }
        }
        // KG neighbors with user-relation attention
        {
            float ux, uy; unpack2(uepk[e], ux, uy);
            int iidx[NS]; float ps[NS];
            #pragma unroll
            for (int s = 0; s < NS; s++){
                ull t = __shfl_sync(0xffffffffu, p_ii, (e << 3) + s);
                float af, bf; unpack2(t, af, bf);
                iidx[s] = __float_as_int(af);
                float2 rf = rel2[__float_as_int(bf)*32 + lane];
                ps[s] = fmaf(ux, rf.x, uy * rf.y);
            }
            // packed butterfly: reduce 8 dots across the warp simultaneously
            ull q0 = pack2(ps[0], ps[1]), q1 = pack2(ps[2], ps[3]);
            ull q2 = pack2(ps[4], ps[5]), q3 = pack2(ps[6], ps[7]);
            #pragma unroll
            for (int o = 16; o; o >>= 1){
                q0 = add2(q0, __shfl_xor_sync(0xffffffffu, q0, o));
                q1 = add2(q1, __shfl_xor_sync(0xffffffffu, q1, o));
                q2 = add2(q2, __shfl_xor_sync(0xffffffffu, q2, o));
                q3 = add2(q3, __shfl_xor_sync(0xffffffffu, q3, o));
            }
            float att[NS];
            unpack2(q0, att[0], att[1]); unpack2(q1, att[2], att[3]);
            unpack2(q2, att[4], att[5]); unpack2(q3, att[6], att[7]);
            softmax8(att);
            float2 f[NS];
            #pragma unroll
            for (int s = 0; s < NS; s++) f[s] = item2[iidx[s]*32 + lane];
            #pragma unroll
            for (int s = 0; s < NS; s++){
                ax = fmaf(att[s], f[s].x, ax);
                ay = fmaf(att[s], f[s].y, ay);
            }
        }
        sxd[warp][e][2*lane]     = pack2(ax, ax);
        sxd[warp][e][2*lane + 1] = pack2(ay, ay);
    }
    __syncwarp();

    // =============== item matvec ===============
    ull vh[EPW];
    matvec((const ull*)Wv, (const ull*)bv, &sxd[warp][0][0], vh, lane);

    // =============== score: sigmoid(dot(user_h, item_h)) * 5 ===============
    float pe[EPW];
    #pragma unroll
    for (int e = 0; e < EPW; e++){
        float a0, a1, b0, b1;
        unpack2(uh[e], a0, a1);
        unpack2(vh[e], b0, b1);
        pe[e] = fmaf(a0, b0, a1 * b1);
    }
    ull s01 = pack2(pe[0], pe[1]), s23 = pack2(pe[2], pe[3]);
    #pragma unroll
    for (int o = 16; o; o >>= 1){
        s01 = add2(s01, __shfl_xor_sync(0xffffffffu, s01, o));
        s23 = add2(s23, __shfl_xor_sync(0xffffffffu, s23, o));
    }
    if (lane == 0){
        float r[EPW];
        unpack2(s01, r[0], r[1]);
        unpack2(s23, r[2], r[3]);
        #pragma unroll
        for (int e = 0; e < EPW; e++)
            if (base + e < batch)
                out[base + e] = 5.f / (1.f + __expf(-r[e]));
    }
}

extern "C" void kernel_launch(void* const* d_in, const int* in_sizes, int n_in,
                              void* d_out, int out_size)
{
    (void)n_in; (void)out_size;
    const int batch = in_sizes[0];
    const int blocks = (batch + WPB*EPW - 1) / (WPB*EPW);
    sestkgcn_kernel<<<blocks, NTHREADS>>>(
        (const int*)d_in[0],  (const int*)d_in[1],
        (const float*)d_in[2], (const float*)d_in[3], (const float*)d_in[4],
        (const int*)d_in[5],  (const float*)d_in[6],
        (const int*)d_in[7],  (const float*)d_in[8],  (const float*)d_in[9],  (const float*)d_in[10],
        (const int*)d_in[11], (const float*)d_in[12], (const float*)d_in[13], (const float*)d_in[14],
        (const int*)d_in[15], (const int*)d_in[16],
        (const float*)d_in[17], (const float*)d_in[18],
        (const float*)d_in[19], (const float*)d_in[20],
        (float*)d_out, batch);
}